// round 10
// baseline (speedup 1.0000x reference)
#include <cuda_runtime.h>

// AggregateJoint: per-row block-diagonal MLP 64 -> (16x16) -> (16x3)
// with leaky_relu + folded batchnorm. Shapes fixed: x (256, 64, 512).
//
// Design (R9): STRAIGHT-LINE threads — one thread = one part x 4 f-columns.
// R4/R7/R8 all pinned at 21-23us with issue ~42% regardless of occ/ILP: the
// serialized per-part loop exposed one DRAM latency window per iteration.
// Here each thread front-batches its 4 LDG.128 x-loads (single exposure),
// does ~350 slots of packed-fp32 math, stores 3 STG.128, exits. 524288
// threads / 2048 CTAs give deep wave churn to overlap load windows.
// Each CTA stages only its 2 parts' weights (~1.1KB, L2-hit) into smem.
// Math: fma.rn.f32x2, pairs along hidden dim; BN folded to scale/shift;
// leaky(x) = 0.505x + 0.495|x| packed.

#define B_DIM 256
#define N_DIM 64
#define F_DIM 512
#define P_DIM 16
#define IN_DIM 4
#define H_DIM 16
#define O_DIM 3
#define COLS 4
#define PARTS_PER_BLK 2

typedef unsigned long long u64;

__device__ __forceinline__ u64 f2fma(u64 a, u64 b, u64 c) {
    u64 d;
    asm("fma.rn.f32x2 %0, %1, %2, %3;" : "=l"(d) : "l"(a), "l"(b), "l"(c));
    return d;
}
__device__ __forceinline__ u64 f2mul(u64 a, u64 b) {
    u64 d;
    asm("mul.rn.f32x2 %0, %1, %2;" : "=l"(d) : "l"(a), "l"(b));
    return d;
}
__device__ __forceinline__ u64 packf2(float lo, float hi) {
    u64 r;
    asm("mov.b64 %0, {%1, %2};" : "=l"(r) : "f"(lo), "f"(hi));
    return r;
}
__device__ __forceinline__ void unpackf2(u64 v, float& lo, float& hi) {
    asm("mov.b64 {%0, %1}, %2;" : "=f"(lo), "=f"(hi) : "l"(v));
}

__global__ __launch_bounds__(256, 2)
void aggregate_joint_kernel(
    const float* __restrict__ x, const int* __restrict__ parts,
    const float* __restrict__ W1, const float* __restrict__ b1,
    const float* __restrict__ W2, const float* __restrict__ b2,
    const float* __restrict__ gamma, const float* __restrict__ beta,
    const float* __restrict__ mean, const float* __restrict__ var,
    float* __restrict__ out)
{
    // per-block staging: only the 2 parts this block computes
    __shared__ __align__(16) float sW1[PARTS_PER_BLK * IN_DIM * H_DIM];   // 128
    __shared__ __align__(16) float sW2T[PARTS_PER_BLK * O_DIM * H_DIM];   // 96
    __shared__ __align__(16) float sB1[PARTS_PER_BLK * H_DIM];            // 32
    __shared__ float sScale[PARTS_PER_BLK * O_DIM];                        // 6
    __shared__ float sShift[PARTS_PER_BLK * O_DIM];                        // 6
    __shared__ int   sN[PARTS_PER_BLK * IN_DIM];                           // 8

    const int tid = threadIdx.x;
    const int b  = blockIdx.x >> 3;                 // batch
    const int p0 = (blockIdx.x & 7) * PARTS_PER_BLK; // first global part

    // ---- stage this block's weights (all L2-resident), fold BN ----
    if (tid < 128) {
        // W1 slice: [2][IN][H] contiguous in global too
        sW1[tid] = W1[p0 * IN_DIM * H_DIM + tid];
    } else if (tid < 224) {
        int idx = tid - 128;                 // 0..95
        int pl = idx / (O_DIM * H_DIM);      // 0/1
        int rem = idx % (O_DIM * H_DIM);
        int o = rem >> 4;
        int hh = rem & 15;
        sW2T[idx] = W2[((p0 + pl) * H_DIM + hh) * O_DIM + o];
    } else {
        int idx = tid - 224;                 // 0..31
        sB1[idx] = b1[p0 * H_DIM + idx];
    }
    if (tid < PARTS_PER_BLK * O_DIM) {
        int g = p0 * O_DIM + tid;
        float s = gamma[g] * rsqrtf(var[g] + 1e-5f);
        sScale[tid] = s;
        sShift[tid] = (b2[g] - mean[g]) * s + beta[g];
    }
    if (tid < PARTS_PER_BLK * IN_DIM)
        sN[tid] = parts[p0 * IN_DIM + tid];
    __syncthreads();

    // ---- this thread: part p_l (0/1), f-quad q (0..127) ----
    const int p_l = tid >> 7;                       // local part
    const int q   = tid & 127;
    const int f   = q << 2;                         // f multiple of 4
    const int p   = p0 + p_l;                       // global part
    const float* xrow = x + (size_t)b * N_DIM * F_DIM + f;
    float* orow = out + ((size_t)b * (P_DIM * O_DIM) + p * O_DIM) * F_DIM + f;

    // front-batched x loads: 4 independent LDG.128 (single latency exposure)
    float4 xc[IN_DIM];
#pragma unroll
    for (int i = 0; i < IN_DIM; i++)
        xc[i] = *(const float4*)&xrow[(size_t)sN[p_l * IN_DIM + i] * F_DIM];

    // leaky(x) = 0.505*x + 0.495*|x|
    const u64 AP = packf2(0.505f, 0.505f);
    const u64 BP = packf2(0.495f, 0.495f);

    // h pairs init from b1 (shared by all 4 columns)
    const ulonglong2* bb = (const ulonglong2*)&sB1[p_l * H_DIM];
    ulonglong2 t0 = bb[0], t1 = bb[1], t2 = bb[2], t3 = bb[3];
    u64 h[COLS][8];
#pragma unroll
    for (int c = 0; c < COLS; c++) {
        h[c][0] = t0.x; h[c][1] = t0.y; h[c][2] = t1.x; h[c][3] = t1.y;
        h[c][4] = t2.x; h[c][5] = t2.y; h[c][6] = t3.x; h[c][7] = t3.y;
    }

    // layer 1: h[c] += x[c][i] * W1[p][i][:]; weight LDS warp-uniform
#pragma unroll
    for (int i = 0; i < IN_DIM; i++) {
        const ulonglong2* wr = (const ulonglong2*)&sW1[(p_l * IN_DIM + i) * H_DIM];
        ulonglong2 w0 = wr[0], w1 = wr[1], w2r = wr[2], w3 = wr[3];
        const u64 w[8] = {w0.x, w0.y, w1.x, w1.y, w2r.x, w2r.y, w3.x, w3.y};
        u64 s[COLS];
        s[0] = packf2(xc[i].x, xc[i].x);
        s[1] = packf2(xc[i].y, xc[i].y);
        s[2] = packf2(xc[i].z, xc[i].z);
        s[3] = packf2(xc[i].w, xc[i].w);
#pragma unroll
        for (int j = 0; j < 8; j++) {
#pragma unroll
            for (int c = 0; c < COLS; c++)
                h[c][j] = f2fma(s[c], w[j], h[c][j]);
        }
    }

    // packed leaky relu
#pragma unroll
    for (int c = 0; c < COLS; c++) {
#pragma unroll
        for (int j = 0; j < 8; j++) {
            u64 ab = h[c][j] & 0x7FFFFFFF7FFFFFFFULL;
            h[c][j] = f2fma(ab, BP, f2mul(h[c][j], AP));
        }
    }

    // layer 2 + BN + leaky + store
#pragma unroll
    for (int o = 0; o < O_DIM; o++) {
        const ulonglong2* wr = (const ulonglong2*)&sW2T[(p_l * O_DIM + o) * H_DIM];
        ulonglong2 a0 = wr[0], a1 = wr[1], a2 = wr[2], a3 = wr[3];
        const u64 a[8] = {a0.x, a0.y, a1.x, a1.y, a2.x, a2.y, a3.x, a3.y};
        u64 acc[COLS];
#pragma unroll
        for (int c = 0; c < COLS; c++)
            acc[c] = f2mul(h[c][0], a[0]);
#pragma unroll
        for (int j = 1; j < 8; j++) {
#pragma unroll
            for (int c = 0; c < COLS; c++)
                acc[c] = f2fma(h[c][j], a[j], acc[c]);
        }
        const float sc = sScale[p_l * O_DIM + o];
        const float sh = sShift[p_l * O_DIM + o];
        float4 vv;
        float lo, hi, v;
        unpackf2(acc[0], lo, hi);
        v = fmaf(lo + hi, sc, sh); vv.x = fmaxf(v, 0.01f * v);
        unpackf2(acc[1], lo, hi);
        v = fmaf(lo + hi, sc, sh); vv.y = fmaxf(v, 0.01f * v);
        unpackf2(acc[2], lo, hi);
        v = fmaf(lo + hi, sc, sh); vv.z = fmaxf(v, 0.01f * v);
        unpackf2(acc[3], lo, hi);
        v = fmaf(lo + hi, sc, sh); vv.w = fmaxf(v, 0.01f * v);
        *(float4*)&orow[(size_t)o * F_DIM] = vv;
    }
}

extern "C" void kernel_launch(void* const* d_in, const int* in_sizes, int n_in,
                              void* d_out, int out_size) {
    const float* x     = (const float*)d_in[0];
    const int*   parts = (const int*)d_in[1];
    const float* W1    = (const float*)d_in[2];
    const float* b1    = (const float*)d_in[3];
    const float* W2    = (const float*)d_in[4];
    const float* b2    = (const float*)d_in[5];
    const float* gamma = (const float*)d_in[6];
    const float* beta  = (const float*)d_in[7];
    const float* mean  = (const float*)d_in[8];
    const float* var   = (const float*)d_in[9];
    float* out = (float*)d_out;

    // grid: 256 batches x 8 part-groups = 2048 CTAs of 256 threads
    // (each thread: 1 part x 4 f-columns; 524288 threads total)
    const int grid = B_DIM * (P_DIM / PARTS_PER_BLK);

    aggregate_joint_kernel<<<grid, 256>>>(x, parts, W1, b1, W2, b2,
                                          gamma, beta, mean, var, out);
}

// round 12
// speedup vs baseline: 1.0014x; 1.0014x over previous
#include <cuda_runtime.h>

// AggregateJoint: per-row block-diagonal MLP 64 -> (16x16) -> (16x3)
// with leaky_relu + folded batchnorm. Shapes fixed: x (256, 64, 512).
//
// Design (R10): straight-line threads (ONE memory exposure) AND high
// occupancy — the one untested cell of the R7/R9 matrix.
// One thread = 1 part x 2 adjacent f columns: h-state 16 u64 (~60 regs),
// __launch_bounds__(256,4) -> 4 CTA/SM -> 50% occ. 1M threads, 4096 CTAs.
// Each CTA stages its 2 parts' weights (~1.1KB, L2-hit). x loads 4x LDG.64
// front-batched; 3x STG.64 stores; packed fp32 (fma.rn.f32x2) math with
// pairs along hidden dim; BN folded; leaky(x)=0.505x+0.495|x| packed.

#define B_DIM 256
#define N_DIM 64
#define F_DIM 512
#define P_DIM 16
#define IN_DIM 4
#define H_DIM 16
#define O_DIM 3
#define PARTS_PER_BLK 2

typedef unsigned long long u64;

__device__ __forceinline__ u64 f2fma(u64 a, u64 b, u64 c) {
    u64 d;
    asm("fma.rn.f32x2 %0, %1, %2, %3;" : "=l"(d) : "l"(a), "l"(b), "l"(c));
    return d;
}
__device__ __forceinline__ u64 f2mul(u64 a, u64 b) {
    u64 d;
    asm("mul.rn.f32x2 %0, %1, %2;" : "=l"(d) : "l"(a), "l"(b));
    return d;
}
__device__ __forceinline__ u64 packf2(float lo, float hi) {
    u64 r;
    asm("mov.b64 %0, {%1, %2};" : "=l"(r) : "f"(lo), "f"(hi));
    return r;
}
__device__ __forceinline__ void unpackf2(u64 v, float& lo, float& hi) {
    asm("mov.b64 {%0, %1}, %2;" : "=f"(lo), "=f"(hi) : "l"(v));
}

__global__ __launch_bounds__(256, 4)
void aggregate_joint_kernel(
    const float* __restrict__ x, const int* __restrict__ parts,
    const float* __restrict__ W1, const float* __restrict__ b1,
    const float* __restrict__ W2, const float* __restrict__ b2,
    const float* __restrict__ gamma, const float* __restrict__ beta,
    const float* __restrict__ mean, const float* __restrict__ var,
    float* __restrict__ out)
{
    __shared__ __align__(16) float sW1[PARTS_PER_BLK * IN_DIM * H_DIM];   // 128
    __shared__ __align__(16) float sW2T[PARTS_PER_BLK * O_DIM * H_DIM];   // 96
    __shared__ __align__(16) float sB1[PARTS_PER_BLK * H_DIM];            // 32
    __shared__ float sScale[PARTS_PER_BLK * O_DIM];                        // 6
    __shared__ float sShift[PARTS_PER_BLK * O_DIM];                        // 6
    __shared__ int   sN[PARTS_PER_BLK * IN_DIM];                           // 8

    const int tid = threadIdx.x;
    // grid = 256 b x 2 f-halves x 8 part-groups = 4096
    const int bx = blockIdx.x;
    const int b  = bx >> 4;
    const int fh = (bx >> 3) & 1;
    const int p0 = (bx & 7) * PARTS_PER_BLK;

    // ---- stage this block's weights (L2-resident), fold BN ----
    if (tid < 128) {
        sW1[tid] = W1[p0 * IN_DIM * H_DIM + tid];
    } else if (tid < 224) {
        int idx = tid - 128;                 // 0..95
        int pl = idx / (O_DIM * H_DIM);
        int rem = idx % (O_DIM * H_DIM);
        int o = rem >> 4;
        int hh = rem & 15;
        sW2T[idx] = W2[((p0 + pl) * H_DIM + hh) * O_DIM + o];
    } else {
        int idx = tid - 224;                 // 0..31
        sB1[idx] = b1[p0 * H_DIM + idx];
    }
    if (tid < PARTS_PER_BLK * O_DIM) {
        int g = p0 * O_DIM + tid;
        float s = gamma[g] * rsqrtf(var[g] + 1e-5f);
        sScale[tid] = s;
        sShift[tid] = (b2[g] - mean[g]) * s + beta[g];
    }
    if (tid < PARTS_PER_BLK * IN_DIM)
        sN[tid] = parts[p0 * IN_DIM + tid];
    __syncthreads();

    // ---- this thread: local part p_l, f-pair within half ----
    const int p_l = tid >> 7;                       // 0/1
    const int q   = tid & 127;
    const int f   = (fh * 128 + q) << 1;            // even f
    const int p   = p0 + p_l;
    const float* xrow = x + (size_t)b * N_DIM * F_DIM + f;
    float* orow = out + ((size_t)b * (P_DIM * O_DIM) + p * O_DIM) * F_DIM + f;

    // front-batched x loads: 4 independent LDG.64 (single latency exposure)
    float2 xc[IN_DIM];
#pragma unroll
    for (int i = 0; i < IN_DIM; i++)
        xc[i] = *(const float2*)&xrow[(size_t)sN[p_l * IN_DIM + i] * F_DIM];

    // leaky(x) = 0.505*x + 0.495*|x|
    const u64 AP = packf2(0.505f, 0.505f);
    const u64 BP = packf2(0.495f, 0.495f);

    // h pairs init from b1 (shared by both columns)
    const ulonglong2* bb = (const ulonglong2*)&sB1[p_l * H_DIM];
    ulonglong2 t0 = bb[0], t1 = bb[1], t2 = bb[2], t3 = bb[3];
    u64 ha[8] = {t0.x, t0.y, t1.x, t1.y, t2.x, t2.y, t3.x, t3.y};
    u64 hb[8] = {t0.x, t0.y, t1.x, t1.y, t2.x, t2.y, t3.x, t3.y};

    // layer 1: weights LDS'd once per i (warp-uniform, broadcast)
#pragma unroll
    for (int i = 0; i < IN_DIM; i++) {
        const ulonglong2* wr = (const ulonglong2*)&sW1[(p_l * IN_DIM + i) * H_DIM];
        ulonglong2 w0 = wr[0], w1 = wr[1], w2r = wr[2], w3 = wr[3];
        u64 sa = packf2(xc[i].x, xc[i].x);
        u64 sb = packf2(xc[i].y, xc[i].y);
        ha[0] = f2fma(sa, w0.x, ha[0]);  hb[0] = f2fma(sb, w0.x, hb[0]);
        ha[1] = f2fma(sa, w0.y, ha[1]);  hb[1] = f2fma(sb, w0.y, hb[1]);
        ha[2] = f2fma(sa, w1.x, ha[2]);  hb[2] = f2fma(sb, w1.x, hb[2]);
        ha[3] = f2fma(sa, w1.y, ha[3]);  hb[3] = f2fma(sb, w1.y, hb[3]);
        ha[4] = f2fma(sa, w2r.x, ha[4]); hb[4] = f2fma(sb, w2r.x, hb[4]);
        ha[5] = f2fma(sa, w2r.y, ha[5]); hb[5] = f2fma(sb, w2r.y, hb[5]);
        ha[6] = f2fma(sa, w3.x, ha[6]);  hb[6] = f2fma(sb, w3.x, hb[6]);
        ha[7] = f2fma(sa, w3.y, ha[7]);  hb[7] = f2fma(sb, w3.y, hb[7]);
    }

    // packed leaky relu
#pragma unroll
    for (int j = 0; j < 8; j++) {
        u64 aa = ha[j] & 0x7FFFFFFF7FFFFFFFULL;
        ha[j] = f2fma(aa, BP, f2mul(ha[j], AP));
        u64 ab = hb[j] & 0x7FFFFFFF7FFFFFFFULL;
        hb[j] = f2fma(ab, BP, f2mul(hb[j], AP));
    }

    // layer 2 + BN + leaky + store
#pragma unroll
    for (int o = 0; o < O_DIM; o++) {
        const ulonglong2* wr = (const ulonglong2*)&sW2T[(p_l * O_DIM + o) * H_DIM];
        ulonglong2 a0 = wr[0], a1 = wr[1], a2 = wr[2], a3 = wr[3];
        u64 acca = f2mul(ha[0], a0.x);
        u64 accb = f2mul(hb[0], a0.x);
        acca = f2fma(ha[1], a0.y, acca);  accb = f2fma(hb[1], a0.y, accb);
        acca = f2fma(ha[2], a1.x, acca);  accb = f2fma(hb[2], a1.x, accb);
        acca = f2fma(ha[3], a1.y, acca);  accb = f2fma(hb[3], a1.y, accb);
        acca = f2fma(ha[4], a2.x, acca);  accb = f2fma(hb[4], a2.x, accb);
        acca = f2fma(ha[5], a2.y, acca);  accb = f2fma(hb[5], a2.y, accb);
        acca = f2fma(ha[6], a3.x, acca);  accb = f2fma(hb[6], a3.x, accb);
        acca = f2fma(ha[7], a3.y, acca);  accb = f2fma(hb[7], a3.y, accb);

        float la, hA, lb, hB;
        unpackf2(acca, la, hA);
        unpackf2(accb, lb, hB);
        const float sc = sScale[p_l * O_DIM + o];
        const float sh = sShift[p_l * O_DIM + o];
        float va = fmaf(la + hA, sc, sh);
        float vb = fmaf(lb + hB, sc, sh);
        va = fmaxf(va, 0.01f * va);
        vb = fmaxf(vb, 0.01f * vb);
        *(float2*)&orow[(size_t)o * F_DIM] = make_float2(va, vb);
    }
}

extern "C" void kernel_launch(void* const* d_in, const int* in_sizes, int n_in,
                              void* d_out, int out_size) {
    const float* x     = (const float*)d_in[0];
    const int*   parts = (const int*)d_in[1];
    const float* W1    = (const float*)d_in[2];
    const float* b1    = (const float*)d_in[3];
    const float* W2    = (const float*)d_in[4];
    const float* b2    = (const float*)d_in[5];
    const float* gamma = (const float*)d_in[6];
    const float* beta  = (const float*)d_in[7];
    const float* mean  = (const float*)d_in[8];
    const float* var   = (const float*)d_in[9];
    float* out = (float*)d_out;

    // grid: 256 batches x 2 f-halves x 8 part-groups = 4096 CTAs x 256 thr
    const int grid = B_DIM * 2 * (P_DIM / PARTS_PER_BLK);

    aggregate_joint_kernel<<<grid, 256>>>(x, parts, W1, b1, W2, b2,
                                          gamma, beta, mean, var, out);
}

// round 13
// speedup vs baseline: 1.1974x; 1.1957x over previous
#include <cuda_runtime.h>

// AggregateJoint: per-row block-diagonal MLP 64 -> (16x16) -> (16x3)
// with leaky_relu + folded batchnorm. Shapes fixed: x (256, 64, 512).
//
// Design (R13): SINGLE-WAVE, part-resident CTAs, f-loop.
// R4..R10 swept occ/ILP/exposure: all 21-23us, issue pinned ~44%. Best was
// R8 = fewest issue-slots/output. So: minimize total instructions AND wave
// overhead. 256 CTAs (one wave @2 CTA/SM), each CTA = one part (weights
// staged once, 1.1KB), each thread loops 8 f-quads at constant f / b+=32
// (2 IADDs per iter of address math, independent iterations, 4 front-
// batched LDG.128 per iter). Math: packed fp32 fma.rn.f32x2, pairs along
// hidden dim; BN folded; leaky(x)=0.505x+0.495|x| packed.

#define B_DIM 256
#define N_DIM 64
#define F_DIM 512
#define P_DIM 16
#define IN_DIM 4
#define H_DIM 16
#define O_DIM 3
#define COLS 4
#define K_ITERS 8

typedef unsigned long long u64;

__device__ __forceinline__ u64 f2fma(u64 a, u64 b, u64 c) {
    u64 d;
    asm("fma.rn.f32x2 %0, %1, %2, %3;" : "=l"(d) : "l"(a), "l"(b), "l"(c));
    return d;
}
__device__ __forceinline__ u64 f2mul(u64 a, u64 b) {
    u64 d;
    asm("mul.rn.f32x2 %0, %1, %2;" : "=l"(d) : "l"(a), "l"(b));
    return d;
}
__device__ __forceinline__ u64 packf2(float lo, float hi) {
    u64 r;
    asm("mov.b64 %0, {%1, %2};" : "=l"(r) : "f"(lo), "f"(hi));
    return r;
}
__device__ __forceinline__ void unpackf2(u64 v, float& lo, float& hi) {
    asm("mov.b64 {%0, %1}, %2;" : "=f"(lo), "=f"(hi) : "l"(v));
}

__global__ __launch_bounds__(256, 2)
void aggregate_joint_kernel(
    const float* __restrict__ x, const int* __restrict__ parts,
    const float* __restrict__ W1, const float* __restrict__ b1,
    const float* __restrict__ W2, const float* __restrict__ b2,
    const float* __restrict__ gamma, const float* __restrict__ beta,
    const float* __restrict__ mean, const float* __restrict__ var,
    float* __restrict__ out)
{
    // this CTA's single part
    __shared__ __align__(16) float sW1[IN_DIM * H_DIM];   // 64
    __shared__ __align__(16) float sW2T[O_DIM * H_DIM];   // 48
    __shared__ __align__(16) float sB1[H_DIM];            // 16
    __shared__ float sSc[O_DIM];
    __shared__ float sSh[O_DIM];
    __shared__ int   sNi[IN_DIM];

    const int tid = threadIdx.x;
    const int p   = blockIdx.x & 15;        // part
    const int cip = blockIdx.x >> 4;        // cta-in-part, 0..15

    // ---- stage this part's weights (L2-hit after first CTA), fold BN ----
    if (tid < 64) {
        sW1[tid] = W1[p * (IN_DIM * H_DIM) + tid];
    } else if (tid < 112) {
        int idx = tid - 64;                 // 0..47
        int o = idx >> 4;
        int hh = idx & 15;
        sW2T[idx] = W2[(p * H_DIM + hh) * O_DIM + o];
    } else if (tid < 128) {
        sB1[tid - 112] = b1[p * H_DIM + (tid - 112)];
    } else if (tid < 128 + O_DIM) {
        int o = tid - 128;
        int g = p * O_DIM + o;
        float s = gamma[g] * rsqrtf(var[g] + 1e-5f);
        sSc[o] = s;
        sSh[o] = (b2[g] - mean[g]) * s + beta[g];
    } else if (tid < 128 + O_DIM + IN_DIM) {
        int i = tid - (128 + O_DIM);
        sNi[i] = parts[p * IN_DIM + i];
    }
    __syncthreads();

    // ---- thread work: 8 iterations, constant f, b = b0 + 32k ----
    const int T    = cip * 256 + tid;       // 0..4095
    const int col0 = T << 2;                // 0..16383
    const int b0   = col0 >> 9;             // 0..31
    const int f    = col0 & 511;            // multiple of 4

    const float* xp = x + ((size_t)b0 << 15) + f;                 // b0*64*512 + f
    float* op = out + (size_t)b0 * 24576 + (size_t)p * 1536 + f;  // (b0*48+p*3)*512 + f

    // x element offsets for this part's 4 inputs (warp-uniform)
    const int n0 = sNi[0] * F_DIM;
    const int n1 = sNi[1] * F_DIM;
    const int n2 = sNi[2] * F_DIM;
    const int n3 = sNi[3] * F_DIM;

    // leaky(x) = 0.505*x + 0.495*|x|
    const u64 AP = packf2(0.505f, 0.505f);
    const u64 BP = packf2(0.495f, 0.495f);

#pragma unroll 1
    for (int k = 0; k < K_ITERS; k++) {
        // front-batched independent loads (MLP=4)
        float4 xc0 = *(const float4*)(xp + n0);
        float4 xc1 = *(const float4*)(xp + n1);
        float4 xc2 = *(const float4*)(xp + n2);
        float4 xc3 = *(const float4*)(xp + n3);

        // h pairs init from b1 (shared by 4 columns)
        const ulonglong2* bb = (const ulonglong2*)sB1;
        ulonglong2 t0 = bb[0], t1 = bb[1], t2 = bb[2], t3 = bb[3];
        u64 h[COLS][8];
#pragma unroll
        for (int c = 0; c < COLS; c++) {
            h[c][0] = t0.x; h[c][1] = t0.y; h[c][2] = t1.x; h[c][3] = t1.y;
            h[c][4] = t2.x; h[c][5] = t2.y; h[c][6] = t3.x; h[c][7] = t3.y;
        }

        // layer 1: weights LDS'd once per i (broadcast), 4 independent chains
#pragma unroll
        for (int i = 0; i < IN_DIM; i++) {
            const ulonglong2* wr = (const ulonglong2*)&sW1[i * H_DIM];
            ulonglong2 w0 = wr[0], w1 = wr[1], w2r = wr[2], w3 = wr[3];
            const u64 w[8] = {w0.x, w0.y, w1.x, w1.y, w2r.x, w2r.y, w3.x, w3.y};
            float4 xi = (i == 0) ? xc0 : (i == 1) ? xc1 : (i == 2) ? xc2 : xc3;
            u64 s[COLS];
            s[0] = packf2(xi.x, xi.x);
            s[1] = packf2(xi.y, xi.y);
            s[2] = packf2(xi.z, xi.z);
            s[3] = packf2(xi.w, xi.w);
#pragma unroll
            for (int j = 0; j < 8; j++) {
#pragma unroll
                for (int c = 0; c < COLS; c++)
                    h[c][j] = f2fma(s[c], w[j], h[c][j]);
            }
        }

        // packed leaky relu
#pragma unroll
        for (int c = 0; c < COLS; c++) {
#pragma unroll
            for (int j = 0; j < 8; j++) {
                u64 ab = h[c][j] & 0x7FFFFFFF7FFFFFFFULL;
                h[c][j] = f2fma(ab, BP, f2mul(h[c][j], AP));
            }
        }

        // layer 2 + BN + leaky + store
#pragma unroll
        for (int o = 0; o < O_DIM; o++) {
            const ulonglong2* wr = (const ulonglong2*)&sW2T[o * H_DIM];
            ulonglong2 a0 = wr[0], a1 = wr[1], a2 = wr[2], a3 = wr[3];
            const u64 a[8] = {a0.x, a0.y, a1.x, a1.y, a2.x, a2.y, a3.x, a3.y};
            u64 acc[COLS];
#pragma unroll
            for (int c = 0; c < COLS; c++)
                acc[c] = f2mul(h[c][0], a[0]);
#pragma unroll
            for (int j = 1; j < 8; j++) {
#pragma unroll
                for (int c = 0; c < COLS; c++)
                    acc[c] = f2fma(h[c][j], a[j], acc[c]);
            }
            const float sc = sSc[o];
            const float sh = sSh[o];
            float4 vv;
            float lo, hi, v;
            unpackf2(acc[0], lo, hi);
            v = fmaf(lo + hi, sc, sh); vv.x = fmaxf(v, 0.01f * v);
            unpackf2(acc[1], lo, hi);
            v = fmaf(lo + hi, sc, sh); vv.y = fmaxf(v, 0.01f * v);
            unpackf2(acc[2], lo, hi);
            v = fmaf(lo + hi, sc, sh); vv.z = fmaxf(v, 0.01f * v);
            unpackf2(acc[3], lo, hi);
            v = fmaf(lo + hi, sc, sh); vv.w = fmaxf(v, 0.01f * v);
            *(float4*)(op + (size_t)o * F_DIM) = vv;
        }

        // constant strides: b += 32
        xp += (1 << 20);        // 32 * 64 * 512 floats
        op += 786432;           // 32 * 48 * 512 floats
    }
}

extern "C" void kernel_launch(void* const* d_in, const int* in_sizes, int n_in,
                              void* d_out, int out_size) {
    const float* x     = (const float*)d_in[0];
    const int*   parts = (const int*)d_in[1];
    const float* W1    = (const float*)d_in[2];
    const float* b1    = (const float*)d_in[3];
    const float* W2    = (const float*)d_in[4];
    const float* b2    = (const float*)d_in[5];
    const float* gamma = (const float*)d_in[6];
    const float* beta  = (const float*)d_in[7];
    const float* mean  = (const float*)d_in[8];
    const float* var   = (const float*)d_in[9];
    float* out = (float*)d_out;

    // 256 CTAs (16 parts x 16 CTAs/part) x 256 threads — single wave
    aggregate_joint_kernel<<<256, 256>>>(x, parts, W1, b1, W2, b2,
                                         gamma, beta, mean, var, out);
}